// round 9
// baseline (speedup 1.0000x reference)
#include <cuda_runtime.h>

#define BATCH 32
#define CCH   84
#define ANCH  8400
#define KTOP  1000
#define CAP   2048            // max compacted candidates per image (expected ~105)
#define BPI   5               // blocks per image
#define APB   1680            // anchors per block segment (5*1680 = 8400)
#define NTH   1024

// Key = (f32 bits of conf << 32) | (~anchor_idx): DESCENDING key order gives
// conf desc then anchor idx asc (lax.top_k tie rule). Keys are unique.
// All device globals zero-init at module load; each is reset by its consumer
// every run so graph replays see identical initial state.
__device__ int                g_count[BATCH];
__device__ unsigned long long g_keys[BATCH][CAP];
__device__ int                g_done[BATCH];

__global__ void __launch_bounds__(NTH, 1) fused_detect_kernel(
    const float* __restrict__ preds, float* __restrict__ out)
{
    const int tid = threadIdx.x;
    const int b   = blockIdx.x / BPI;      // image
    const int s   = blockIdx.x % BPI;      // segment within image

    // ---- Phase 1a: zero this image's share of the output slab ----
    // 1500 float4 per image, 300 per segment block.
    {
        float4* o4 = (float4*)(out + (size_t)b * KTOP * 6);
        if (tid < 300) o4[s * 300 + tid] = make_float4(0.f, 0.f, 0.f, 0.f);
    }

    // ---- Phase 1b: score compact for anchors [s*APB, (s+1)*APB) ----
    const float* pb = preds + (size_t)b * CCH * ANCH;
#pragma unroll
    for (int k = 0; k < 2; ++k) {
        const int off = k * NTH + tid;
        if (off < APB) {
            const int a = s * APB + off;
            const float* p = pb + a;
            const float s0 = p[4 * ANCH];          // class-0 score

            // Stage 1: classes 5..20 (16 independent, pipelined LDGs).
            float rest = -1.0f;
#pragma unroll
            for (int c = 5; c < 21; ++c)
                rest = fmaxf(rest, p[(size_t)c * ANCH]);

            if (s0 > 0.1f && s0 >= rest) {
                // Stage 2: classes 21..83 (~6% of anchors).
#pragma unroll 21
                for (int c = 21; c < CCH; ++c)
                    rest = fmaxf(rest, p[(size_t)c * ANCH]);

                if (s0 >= rest) {          // argmax==0 (first-occurrence) & conf>thr
                    int pos = atomicAdd(&g_count[b], 1);
                    if (pos < CAP)
                        g_keys[b][pos] =
                            ((unsigned long long)__float_as_uint(s0) << 32)
                            | (unsigned)(0xFFFFFFFFu - (unsigned)a);
                }
            }
        }
    }

    // ---- Per-image arrival (release) ----
    __syncthreads();
    if (tid == 0) {
        __threadfence();                   // release keys/zeroed-slab writes
        atomicAdd(&g_done[b], 1);
    }
    if (s != 0) return;                    // only segment-0 blocks run NMS

    // ---- Wait for this image's 5 segments (acquire) ----
    if (tid == 0) {
        while (*((volatile int*)&g_done[b]) != BPI) { __nanosleep(32); }
        g_done[b] = 0;                     // reset for next replay
        __threadfence();
    }
    __syncthreads();

    // ---------------- Phase 2: per-image sort + NMS + emit ----------------
    const int NT = NTH;

    __shared__ unsigned long long keys[CAP];
    __shared__ float bx1[1024], by1[1024], bx2[1024], by2[1024], barea[1024];
    __shared__ short perm[1024];           // sorted pos -> smem slot
    __shared__ unsigned char keep[1024];
    __shared__ unsigned mask[256][8];      // suppression bits (sorted space), n<=256
    __shared__ unsigned rowAny[8];         // bit i: row i has ANY suppression bit
    __shared__ unsigned keepw[8];

    float* o = out + (size_t)b * KTOP * 6;

    int cnt = __ldcg(&g_count[b]);
    if (cnt > CAP) cnt = CAP;
    for (int i = tid; i < cnt; i += NT) keys[i] = __ldcg(&g_keys[b][i]);
    __syncthreads();
    if (tid == 0) g_count[b] = 0;          // reset for next replay

    const float* p = pb;
    const int n = (cnt < KTOP) ? cnt : KTOP;

    if (cnt <= 256) {
        // Gather boxes in UNSORTED candidate order (overlaps the rank loop's
        // latency with the scattered LDGs) and compute ranks in parallel.
        if (tid < cnt) {
            int r = tid;
            int idx = (int)(0xFFFFFFFFu - (unsigned)keys[r]);
            float cx = p[idx];
            float cy = p[ANCH + idx];
            float w  = p[2 * ANCH + idx];
            float h  = p[3 * ANCH + idx];

            unsigned long long k = keys[r];
            int rank = 0;
            for (int j = 0; j < cnt; ++j) rank += (keys[j] > k);
            perm[rank] = (short)r;

            float hw = __fmul_rn(w, 0.5f), hh = __fmul_rn(h, 0.5f);
            float x1 = __fsub_rn(cx, hw), y1 = __fsub_rn(cy, hh);
            float x2 = __fadd_rn(cx, hw), y2 = __fadd_rn(cy, hh);
            bx1[r] = x1; by1[r] = y1; bx2[r] = x2; by2[r] = y2;
            barea[r] = __fmul_rn(__fsub_rn(x2, x1), __fsub_rn(y2, y1));
        }
        for (int i = tid; i < n * 8; i += NT) ((unsigned*)mask)[i] = 0u;
        if (tid < 8) rowAny[tid] = 0u;
        __syncthreads();

        // Pairwise IoU in sorted space: bit j of mask[i] = iou(sorted i, sorted j) > thr.
        {
            int total = n * n;
            int t = tid;
            if (t < total) {
                int i = t / n;
                int j = t - i * n;
                for (; t < total; t += NT) {
                    if (j > i) {
                        int pi = perm[i], pj = perm[j];
                        float xx1 = fmaxf(bx1[pi], bx1[pj]);
                        float yy1 = fmaxf(by1[pi], by1[pj]);
                        float xx2 = fminf(bx2[pi], bx2[pj]);
                        float yy2 = fminf(by2[pi], by2[pj]);
                        float iw  = fmaxf(__fsub_rn(xx2, xx1), 0.0f);
                        float ih  = fmaxf(__fsub_rn(yy2, yy1), 0.0f);
                        float inter = __fmul_rn(iw, ih);
                        float denom = __fadd_rn(
                            __fsub_rn(__fadd_rn(barea[pi], barea[pj]), inter), 1e-7f);
                        if (__fdiv_rn(inter, denom) > 0.7f) {
                            atomicOr(&mask[i][j >> 5], 1u << (j & 31));
                            atomicOr(&rowAny[i >> 5], 1u << (i & 31));
                        }
                    }
                    j += NT;
                    while (j >= n) { j -= n; ++i; }
                }
            }
        }
        __syncthreads();

        // Sparse warp sweep over suppressing rows only.
        if (tid < 32) {
            const int lane = tid;
            unsigned kw = 0;
            if (lane < 8) {
                int lo = lane * 32;
                kw = (n >= lo + 32) ? 0xFFFFFFFFu
                   : (n <= lo ? 0u : ((1u << (n - lo)) - 1u));
            }
#pragma unroll
            for (int w = 0; w < 8; ++w) {
                unsigned ra = rowAny[w];
                while (ra) {
                    int bit = __ffs(ra) - 1;
                    ra &= ra - 1u;
                    int i = w * 32 + bit;
                    unsigned m = (lane < 8) ? mask[i][lane] : 0u;
                    unsigned kwi = __shfl_sync(0xFFFFFFFFu, kw, w);
                    if ((kwi >> bit) & 1u)
                        kw &= ~m;
                }
            }
            if (lane < 8) keepw[lane] = kw;
        }
        __syncthreads();

        // Emit kept rows (slab already zeroed in phase 1a).
        const float SCALE_F = 0.3333333333333333f;
        if (tid < n) {
            int r = tid;
            if ((keepw[r >> 5] >> (r & 31)) & 1u) {
                int pr = perm[r];
                float conf = __uint_as_float((unsigned)(keys[pr] >> 32));
                o[r * 6 + 0] = __fdiv_rn(bx1[pr], SCALE_F);
                o[r * 6 + 1] = __fdiv_rn(by1[pr], SCALE_F);
                o[r * 6 + 2] = __fdiv_rn(bx2[pr], SCALE_F);
                o[r * 6 + 3] = __fdiv_rn(by2[pr], SCALE_F);
                o[r * 6 + 4] = conf;
                // o[r*6+5] stays 0 (cls)
            }
        }
    } else {
        // ---- Fallback (statistically never taken): bitonic sort + sequential NMS ----
        int m = 1; while (m < cnt) m <<= 1;
        for (int i = cnt + tid; i < m; i += NT) keys[i] = 0ull;
        __syncthreads();
        for (int k = 2; k <= m; k <<= 1)
            for (int j = k >> 1; j > 0; j >>= 1) {
                for (int i = tid; i < m; i += NT) {
                    int ixj = i ^ j;
                    if (ixj > i) {
                        unsigned long long u = keys[i], v = keys[ixj];
                        bool desc = ((i & k) == 0);
                        if ((u < v) == desc) { keys[i] = v; keys[ixj] = u; }
                    }
                }
                __syncthreads();
            }
        for (int r = tid; r < n; r += NT) {
            int idx = (int)(0xFFFFFFFFu - (unsigned)keys[r]);
            float cx = p[idx];
            float cy = p[ANCH + idx];
            float w  = p[2 * ANCH + idx];
            float h  = p[3 * ANCH + idx];
            float hw = __fmul_rn(w, 0.5f), hh = __fmul_rn(h, 0.5f);
            float x1 = __fsub_rn(cx, hw), y1 = __fsub_rn(cy, hh);
            float x2 = __fadd_rn(cx, hw), y2 = __fadd_rn(cy, hh);
            bx1[r] = x1; by1[r] = y1; bx2[r] = x2; by2[r] = y2;
            barea[r] = __fmul_rn(__fsub_rn(x2, x1), __fsub_rn(y2, y1));
            keep[r] = 1;
        }
        __syncthreads();
        for (int i = 0; i + 1 < n; ++i) {
            if (keep[i]) {
                float xi1 = bx1[i], yi1 = by1[i], xi2 = bx2[i], yi2 = by2[i];
                float ai  = barea[i];
                for (int j = i + 1 + tid; j < n; j += NT) {
                    if (!keep[j]) continue;
                    float xx1 = fmaxf(xi1, bx1[j]);
                    float yy1 = fmaxf(yi1, by1[j]);
                    float xx2 = fminf(xi2, bx2[j]);
                    float yy2 = fminf(yi2, by2[j]);
                    float iw  = fmaxf(__fsub_rn(xx2, xx1), 0.0f);
                    float ih  = fmaxf(__fsub_rn(yy2, yy1), 0.0f);
                    float inter = __fmul_rn(iw, ih);
                    float denom = __fadd_rn(__fsub_rn(__fadd_rn(ai, barea[j]), inter), 1e-7f);
                    if (__fdiv_rn(inter, denom) > 0.7f) keep[j] = 0;
                }
            }
            __syncthreads();
        }
        const float SCALE_F = 0.3333333333333333f;
        for (int r = tid; r < n; r += NT) {
            if (keep[r]) {
                float conf = __uint_as_float((unsigned)(keys[r] >> 32));
                o[r * 6 + 0] = __fdiv_rn(bx1[r], SCALE_F);
                o[r * 6 + 1] = __fdiv_rn(by1[r], SCALE_F);
                o[r * 6 + 2] = __fdiv_rn(bx2[r], SCALE_F);
                o[r * 6 + 3] = __fdiv_rn(by2[r], SCALE_F);
                o[r * 6 + 4] = conf;
            }
        }
    }
}

extern "C" void kernel_launch(void* const* d_in, const int* in_sizes, int n_in,
                              void* d_out, int out_size) {
    const float* preds = (const float*)d_in[0];
    float* out = (float*)d_out;
    fused_detect_kernel<<<BATCH * BPI, NTH>>>(preds, out);
}

// round 10
// speedup vs baseline: 1.3233x; 1.3233x over previous
#include <cuda_runtime.h>

#define BATCH 32
#define CCH   84
#define ANCH  8400
#define KTOP  1000
#define CAP   2048            // max compacted candidates per image (expected ~105)

// Key = (f32 bits of conf << 32) | (~anchor_idx): DESCENDING key order gives
// conf desc then anchor idx asc (lax.top_k tie rule). Keys are unique.
// g_count is zero-init at module load; nms kernel resets it after consuming.
__device__ int                g_count[BATCH];
__device__ unsigned long long g_keys[BATCH][CAP];

// One thread per (image, anchor). Two-stage scan: 16 classes pipelined, then
// the remaining 63 only for the ~6% of anchors still possibly class-0-max.
// Also zeroes the output slab (spread across the whole grid).
__global__ void __launch_bounds__(256) score_compact_kernel(
    const float* __restrict__ preds, float* __restrict__ out)
{
    const int gtid = blockIdx.x * 256 + threadIdx.x;

    // Zero output slab (48000 float4 across 268800 threads).
    if (gtid < (BATCH * KTOP * 6) / 4)
        ((float4*)out)[gtid] = make_float4(0.f, 0.f, 0.f, 0.f);

    if (gtid >= BATCH * ANCH) return;
    const int b = gtid / ANCH;
    const int a = gtid - b * ANCH;

    const float* p = preds + (size_t)b * CCH * ANCH + a;
    const float s0 = p[4 * ANCH];          // class-0 score

    // Stage 1: classes 5..20 (16 independent, fully pipelined LDGs).
    float rest = -1.0f;
#pragma unroll
    for (int c = 5; c < 21; ++c)
        rest = fmaxf(rest, p[(size_t)c * ANCH]);

    if (s0 > 0.1f && s0 >= rest) {
        // Stage 2: classes 21..83 (only ~6% of anchors get here).
#pragma unroll 21
        for (int c = 21; c < CCH; ++c)
            rest = fmaxf(rest, p[(size_t)c * ANCH]);

        if (s0 >= rest) {                  // argmax==0 (first-occurrence) & conf>thr
            int pos = atomicAdd(&g_count[b], 1);
            if (pos < CAP)
                g_keys[b][pos] =
                    ((unsigned long long)__float_as_uint(s0) << 32)
                    | (unsigned)(0xFFFFFFFFu - (unsigned)a);
        }
    }
}

// One block per image: rank-sort (overlapped with gather), row-per-warp ballot
// IoU masks, sparse warp sweep, emit.
__global__ void __launch_bounds__(1024, 1) sort_nms_out_kernel(
    const float* __restrict__ preds, float* __restrict__ out)
{
    const int b    = blockIdx.x;
    const int tid  = threadIdx.x;
    const int NT   = 1024;
    const int wid  = tid >> 5;
    const int lane = tid & 31;

    __shared__ unsigned long long keys[CAP];
    __shared__ float bx1[1024], by1[1024], bx2[1024], by2[1024], barea[1024];
    __shared__ short perm[1024];           // sorted pos -> smem slot
    __shared__ unsigned char keep[1024];
    __shared__ unsigned mask[256][8];      // suppression bits (sorted space), n<=256
    __shared__ unsigned rowAny[8];         // bit i: row i has ANY suppression bit
    __shared__ unsigned keepw[8];

    float* o = out + (size_t)b * KTOP * 6;

    int cnt = g_count[b];
    if (cnt > CAP) cnt = CAP;
    for (int i = tid; i < cnt; i += NT) keys[i] = g_keys[b][i];
    __syncthreads();
    if (tid == 0) g_count[b] = 0;          // reset for next replay

    const float* p = preds + (size_t)b * CCH * ANCH;
    const int n = (cnt < KTOP) ? cnt : KTOP;

    if (cnt <= 256) {
        // Gather boxes in UNSORTED candidate order (overlaps the rank loop's
        // latency with the scattered LDGs) and compute ranks in parallel.
        if (tid < cnt) {
            int r = tid;
            int idx = (int)(0xFFFFFFFFu - (unsigned)keys[r]);
            float cx = p[idx];              // LDGs issued up front
            float cy = p[ANCH + idx];
            float w  = p[2 * ANCH + idx];
            float h  = p[3 * ANCH + idx];

            unsigned long long k = keys[r];
            int rank = 0;
            for (int j = 0; j < cnt; ++j) rank += (keys[j] > k);
            perm[rank] = (short)r;

            float hw = __fmul_rn(w, 0.5f), hh = __fmul_rn(h, 0.5f);
            float x1 = __fsub_rn(cx, hw), y1 = __fsub_rn(cy, hh);
            float x2 = __fadd_rn(cx, hw), y2 = __fadd_rn(cy, hh);
            bx1[r] = x1; by1[r] = y1; bx2[r] = x2; by2[r] = y2;
            barea[r] = __fmul_rn(__fsub_rn(x2, x1), __fsub_rn(y2, y1));
        }
        for (int i = tid; i < n * 8; i += NT) ((unsigned*)mask)[i] = 0u;
        if (tid < 8) rowAny[tid] = 0u;
        __syncthreads();

        // Row-per-warp IoU mask build (upper triangle only). Warp owns rows
        // i = wid, wid+32, ...; lanes cover j = i+1+lane, +32, ... A single
        // ballot per 32 j's replaces per-bit atomics; row words are
        // warp-exclusive so plain OR suffices.
        for (int i = wid; i < n; i += 32) {
            int pi = perm[i];
            float ix1 = bx1[pi], iy1 = by1[pi], ix2 = bx2[pi], iy2 = by2[pi];
            float ia  = barea[pi];
            bool rowHit = false;
            for (int jbase = i + 1; jbase < n; jbase += 32) {
                int j = jbase + lane;
                bool hit = false;
                if (j < n) {
                    int pj = perm[j];
                    float xx1 = fmaxf(ix1, bx1[pj]);
                    float yy1 = fmaxf(iy1, by1[pj]);
                    float xx2 = fminf(ix2, bx2[pj]);
                    float yy2 = fminf(iy2, by2[pj]);
                    float iw  = fmaxf(__fsub_rn(xx2, xx1), 0.0f);
                    float ih  = fmaxf(__fsub_rn(yy2, yy1), 0.0f);
                    float inter = __fmul_rn(iw, ih);
                    float denom = __fadd_rn(
                        __fsub_rn(__fadd_rn(ia, barea[pj]), inter), 1e-7f);
                    hit = (__fdiv_rn(inter, denom) > 0.7f);
                }
                unsigned bal = __ballot_sync(0xFFFFFFFFu, hit);
                if (bal) {
                    rowHit = true;
                    if (lane == 0) {
                        int w0 = jbase >> 5, sh = jbase & 31;
                        mask[i][w0] |= (bal << sh);
                        if (sh && w0 + 1 < 8) mask[i][w0 + 1] |= (bal >> (32 - sh));
                    }
                }
            }
            if (rowHit && lane == 0)
                atomicOr(&rowAny[i >> 5], 1u << (i & 31));
        }
        __syncthreads();

        // Sparse warp sweep: only rows that suppress something matter (a zero
        // mask row leaves keep unchanged whether or not box i survives).
        if (tid < 32) {
            unsigned kw = 0;
            if (lane < 8) {
                int lo = lane * 32;
                kw = (n >= lo + 32) ? 0xFFFFFFFFu
                   : (n <= lo ? 0u : ((1u << (n - lo)) - 1u));
            }
#pragma unroll
            for (int w = 0; w < 8; ++w) {
                unsigned ra = rowAny[w];               // broadcast; uniform loop
                while (ra) {
                    int bit = __ffs(ra) - 1;
                    ra &= ra - 1u;
                    int i = w * 32 + bit;
                    unsigned m = (lane < 8) ? mask[i][lane] : 0u;
                    unsigned kwi = __shfl_sync(0xFFFFFFFFu, kw, w);
                    if ((kwi >> bit) & 1u)
                        kw &= ~m;
                }
            }
            if (lane < 8) keepw[lane] = kw;
        }
        __syncthreads();

        // Emit kept rows (slab already zeroed by compact kernel).
        const float SCALE_F = 0.3333333333333333f;
        if (tid < n) {
            int r = tid;
            if ((keepw[r >> 5] >> (r & 31)) & 1u) {
                int pr = perm[r];
                float conf = __uint_as_float((unsigned)(keys[pr] >> 32));
                o[r * 6 + 0] = __fdiv_rn(bx1[pr], SCALE_F);
                o[r * 6 + 1] = __fdiv_rn(by1[pr], SCALE_F);
                o[r * 6 + 2] = __fdiv_rn(bx2[pr], SCALE_F);
                o[r * 6 + 3] = __fdiv_rn(by2[pr], SCALE_F);
                o[r * 6 + 4] = conf;
                // o[r*6+5] stays 0 (cls)
            }
        }
    } else {
        // ---- Fallback (statistically never taken): bitonic sort + sequential NMS ----
        int m = 1; while (m < cnt) m <<= 1;
        for (int i = cnt + tid; i < m; i += NT) keys[i] = 0ull;
        __syncthreads();
        for (int k = 2; k <= m; k <<= 1)
            for (int j = k >> 1; j > 0; j >>= 1) {
                for (int i = tid; i < m; i += NT) {
                    int ixj = i ^ j;
                    if (ixj > i) {
                        unsigned long long u = keys[i], v = keys[ixj];
                        bool desc = ((i & k) == 0);
                        if ((u < v) == desc) { keys[i] = v; keys[ixj] = u; }
                    }
                }
                __syncthreads();
            }
        for (int r = tid; r < n; r += NT) {
            int idx = (int)(0xFFFFFFFFu - (unsigned)keys[r]);
            float cx = p[idx];
            float cy = p[ANCH + idx];
            float w  = p[2 * ANCH + idx];
            float h  = p[3 * ANCH + idx];
            float hw = __fmul_rn(w, 0.5f), hh = __fmul_rn(h, 0.5f);
            float x1 = __fsub_rn(cx, hw), y1 = __fsub_rn(cy, hh);
            float x2 = __fadd_rn(cx, hw), y2 = __fadd_rn(cy, hh);
            bx1[r] = x1; by1[r] = y1; bx2[r] = x2; by2[r] = y2;
            barea[r] = __fmul_rn(__fsub_rn(x2, x1), __fsub_rn(y2, y1));
            keep[r] = 1;
        }
        __syncthreads();
        for (int i = 0; i + 1 < n; ++i) {
            if (keep[i]) {
                float xi1 = bx1[i], yi1 = by1[i], xi2 = bx2[i], yi2 = by2[i];
                float ai  = barea[i];
                for (int j = i + 1 + tid; j < n; j += NT) {
                    if (!keep[j]) continue;
                    float xx1 = fmaxf(xi1, bx1[j]);
                    float yy1 = fmaxf(yi1, by1[j]);
                    float xx2 = fminf(xi2, bx2[j]);
                    float yy2 = fminf(yi2, by2[j]);
                    float iw  = fmaxf(__fsub_rn(xx2, xx1), 0.0f);
                    float ih  = fmaxf(__fsub_rn(yy2, yy1), 0.0f);
                    float inter = __fmul_rn(iw, ih);
                    float denom = __fadd_rn(__fsub_rn(__fadd_rn(ai, barea[j]), inter), 1e-7f);
                    if (__fdiv_rn(inter, denom) > 0.7f) keep[j] = 0;
                }
            }
            __syncthreads();
        }
        const float SCALE_F = 0.3333333333333333f;
        for (int r = tid; r < n; r += NT) {
            if (keep[r]) {
                float conf = __uint_as_float((unsigned)(keys[r] >> 32));
                o[r * 6 + 0] = __fdiv_rn(bx1[r], SCALE_F);
                o[r * 6 + 1] = __fdiv_rn(by1[r], SCALE_F);
                o[r * 6 + 2] = __fdiv_rn(bx2[r], SCALE_F);
                o[r * 6 + 3] = __fdiv_rn(by2[r], SCALE_F);
                o[r * 6 + 4] = conf;
            }
        }
    }
}

extern "C" void kernel_launch(void* const* d_in, const int* in_sizes, int n_in,
                              void* d_out, int out_size) {
    const float* preds = (const float*)d_in[0];
    float* out = (float*)d_out;

    score_compact_kernel<<<(BATCH * ANCH + 255) / 256, 256>>>(preds, out);
    sort_nms_out_kernel<<<BATCH, 1024>>>(preds, out);
}

// round 11
// speedup vs baseline: 1.4129x; 1.0677x over previous
#include <cuda_runtime.h>

#define BATCH 32
#define CCH   84
#define ANCH  8400
#define KTOP  1000
#define CAP   2048            // max compacted candidates per image (expected ~105)

// Key = (f32 bits of conf << 32) | (~anchor_idx): DESCENDING key order gives
// conf desc then anchor idx asc (lax.top_k tie rule). Keys are unique.
// g_count is zero-init at module load; nms kernel resets it after consuming.
// g_boxes[b][pos] = {x1,y1,x2,y2} computed reference-exact in the compact kernel.
__device__ int                g_count[BATCH];
__device__ unsigned long long g_keys[BATCH][CAP];
__device__ float4             g_boxes[BATCH][CAP];

// One thread per (image, anchor). Two-stage scan: 16 classes pipelined, then
// the remaining 63 only for the ~6% of anchors still possibly class-0-max.
// Winners also load cx,cy,w,h and store the xyxy box (removes the scattered
// gather from the NMS kernel's critical path). Also zeroes the output slab.
__global__ void __launch_bounds__(256) score_compact_kernel(
    const float* __restrict__ preds, float* __restrict__ out)
{
    const int gtid = blockIdx.x * 256 + threadIdx.x;

    // Zero output slab (48000 float4 across 268800 threads).
    if (gtid < (BATCH * KTOP * 6) / 4)
        ((float4*)out)[gtid] = make_float4(0.f, 0.f, 0.f, 0.f);

    if (gtid >= BATCH * ANCH) return;
    const int b = gtid / ANCH;
    const int a = gtid - b * ANCH;

    const float* p = preds + (size_t)b * CCH * ANCH + a;
    const float s0 = p[4 * ANCH];          // class-0 score

    // Stage 1: classes 5..20 (16 independent, fully pipelined LDGs).
    float rest = -1.0f;
#pragma unroll
    for (int c = 5; c < 21; ++c)
        rest = fmaxf(rest, p[(size_t)c * ANCH]);

    if (s0 > 0.1f && s0 >= rest) {
        // Stage 2: classes 21..83 (only ~6% of anchors get here).
#pragma unroll 21
        for (int c = 21; c < CCH; ++c)
            rest = fmaxf(rest, p[(size_t)c * ANCH]);

        if (s0 >= rest) {                  // argmax==0 (first-occurrence) & conf>thr
            int pos = atomicAdd(&g_count[b], 1);
            if (pos < CAP) {
                g_keys[b][pos] =
                    ((unsigned long long)__float_as_uint(s0) << 32)
                    | (unsigned)(0xFFFFFFFFu - (unsigned)a);
                // Box math, reference op order exactly.
                float cx = p[0];
                float cy = p[ANCH];
                float w  = p[2 * ANCH];
                float h  = p[3 * ANCH];
                float hw = __fmul_rn(w, 0.5f), hh = __fmul_rn(h, 0.5f);
                g_boxes[b][pos] = make_float4(
                    __fsub_rn(cx, hw), __fsub_rn(cy, hh),
                    __fadd_rn(cx, hw), __fadd_rn(cy, hh));
            }
        }
    }
}

// One block per image: rank-sort, row-per-warp ballot IoU masks, sparse warp
// sweep, emit. Boxes arrive precomputed from the compact kernel.
__global__ void __launch_bounds__(1024, 1) sort_nms_out_kernel(
    const float* __restrict__ preds, float* __restrict__ out)
{
    const int b    = blockIdx.x;
    const int tid  = threadIdx.x;
    const int NT   = 1024;
    const int wid  = tid >> 5;
    const int lane = tid & 31;

    __shared__ unsigned long long keys[CAP];
    __shared__ float bx1[1024], by1[1024], bx2[1024], by2[1024], barea[1024];
    __shared__ short perm[1024];           // sorted pos -> smem slot
    __shared__ unsigned char keep[1024];
    __shared__ unsigned mask[256][8];      // suppression bits (sorted space), n<=256
    __shared__ unsigned rowAny[8];         // bit i: row i has ANY suppression bit
    __shared__ unsigned keepw[8];

    float* o = out + (size_t)b * KTOP * 6;

    int cnt = g_count[b];
    if (cnt > CAP) cnt = CAP;
    for (int i = tid; i < cnt; i += NT) keys[i] = g_keys[b][i];
    __syncthreads();
    if (tid == 0) g_count[b] = 0;          // reset for next replay

    const int n = (cnt < KTOP) ? cnt : KTOP;

    if (cnt <= 256) {
        // Load precomputed box, compute rank in parallel (box load overlaps
        // the rank loop's smem reads).
        if (tid < cnt) {
            int r = tid;
            float4 bb = g_boxes[b][r];      // LDG issued up front

            unsigned long long k = keys[r];
            int rank = 0;
            for (int j = 0; j < cnt; ++j) rank += (keys[j] > k);
            perm[rank] = (short)r;

            bx1[r] = bb.x; by1[r] = bb.y; bx2[r] = bb.z; by2[r] = bb.w;
            barea[r] = __fmul_rn(__fsub_rn(bb.z, bb.x), __fsub_rn(bb.w, bb.y));
        }
        for (int i = tid; i < n * 8; i += NT) ((unsigned*)mask)[i] = 0u;
        if (tid < 8) rowAny[tid] = 0u;
        __syncthreads();

        // Row-per-warp IoU mask build (upper triangle only). Warp owns rows
        // i = wid, wid+32, ...; lanes cover j = i+1+lane, +32, ... A single
        // ballot per 32 j's replaces per-bit atomics; row words are
        // warp-exclusive so plain OR suffices.
        for (int i = wid; i < n; i += 32) {
            int pi = perm[i];
            float ix1 = bx1[pi], iy1 = by1[pi], ix2 = bx2[pi], iy2 = by2[pi];
            float ia  = barea[pi];
            bool rowHit = false;
            for (int jbase = i + 1; jbase < n; jbase += 32) {
                int j = jbase + lane;
                bool hit = false;
                if (j < n) {
                    int pj = perm[j];
                    float xx1 = fmaxf(ix1, bx1[pj]);
                    float yy1 = fmaxf(iy1, by1[pj]);
                    float xx2 = fminf(ix2, bx2[pj]);
                    float yy2 = fminf(iy2, by2[pj]);
                    float iw  = fmaxf(__fsub_rn(xx2, xx1), 0.0f);
                    float ih  = fmaxf(__fsub_rn(yy2, yy1), 0.0f);
                    float inter = __fmul_rn(iw, ih);
                    float denom = __fadd_rn(
                        __fsub_rn(__fadd_rn(ia, barea[pj]), inter), 1e-7f);
                    hit = (__fdiv_rn(inter, denom) > 0.7f);
                }
                unsigned bal = __ballot_sync(0xFFFFFFFFu, hit);
                if (bal) {
                    rowHit = true;
                    if (lane == 0) {
                        int w0 = jbase >> 5, sh = jbase & 31;
                        mask[i][w0] |= (bal << sh);
                        if (sh && w0 + 1 < 8) mask[i][w0 + 1] |= (bal >> (32 - sh));
                    }
                }
            }
            if (rowHit && lane == 0)
                atomicOr(&rowAny[i >> 5], 1u << (i & 31));
        }
        __syncthreads();

        // Sparse warp sweep: only rows that suppress something matter (a zero
        // mask row leaves keep unchanged whether or not box i survives).
        if (tid < 32) {
            unsigned kw = 0;
            if (lane < 8) {
                int lo = lane * 32;
                kw = (n >= lo + 32) ? 0xFFFFFFFFu
                   : (n <= lo ? 0u : ((1u << (n - lo)) - 1u));
            }
#pragma unroll
            for (int w = 0; w < 8; ++w) {
                unsigned ra = rowAny[w];               // broadcast; uniform loop
                while (ra) {
                    int bit = __ffs(ra) - 1;
                    ra &= ra - 1u;
                    int i = w * 32 + bit;
                    unsigned m = (lane < 8) ? mask[i][lane] : 0u;
                    unsigned kwi = __shfl_sync(0xFFFFFFFFu, kw, w);
                    if ((kwi >> bit) & 1u)
                        kw &= ~m;
                }
            }
            if (lane < 8) keepw[lane] = kw;
        }
        __syncthreads();

        // Emit kept rows (slab already zeroed by compact kernel).
        const float SCALE_F = 0.3333333333333333f;
        if (tid < n) {
            int r = tid;
            if ((keepw[r >> 5] >> (r & 31)) & 1u) {
                int pr = perm[r];
                float conf = __uint_as_float((unsigned)(keys[pr] >> 32));
                o[r * 6 + 0] = __fdiv_rn(bx1[pr], SCALE_F);
                o[r * 6 + 1] = __fdiv_rn(by1[pr], SCALE_F);
                o[r * 6 + 2] = __fdiv_rn(bx2[pr], SCALE_F);
                o[r * 6 + 3] = __fdiv_rn(by2[pr], SCALE_F);
                o[r * 6 + 4] = conf;
                // o[r*6+5] stays 0 (cls)
            }
        }
    } else {
        // ---- Fallback (statistically never taken): bitonic sort + sequential NMS ----
        int m = 1; while (m < cnt) m <<= 1;
        for (int i = cnt + tid; i < m; i += NT) keys[i] = 0ull;
        __syncthreads();
        for (int k = 2; k <= m; k <<= 1)
            for (int j = k >> 1; j > 0; j >>= 1) {
                for (int i = tid; i < m; i += NT) {
                    int ixj = i ^ j;
                    if (ixj > i) {
                        unsigned long long u = keys[i], v = keys[ixj];
                        bool desc = ((i & k) == 0);
                        if ((u < v) == desc) { keys[i] = v; keys[ixj] = u; }
                    }
                }
                __syncthreads();
            }
        const float* p = preds + (size_t)b * CCH * ANCH;
        for (int r = tid; r < n; r += NT) {
            int idx = (int)(0xFFFFFFFFu - (unsigned)keys[r]);
            float cx = p[idx];
            float cy = p[ANCH + idx];
            float w  = p[2 * ANCH + idx];
            float h  = p[3 * ANCH + idx];
            float hw = __fmul_rn(w, 0.5f), hh = __fmul_rn(h, 0.5f);
            float x1 = __fsub_rn(cx, hw), y1 = __fsub_rn(cy, hh);
            float x2 = __fadd_rn(cx, hw), y2 = __fadd_rn(cy, hh);
            bx1[r] = x1; by1[r] = y1; bx2[r] = x2; by2[r] = y2;
            barea[r] = __fmul_rn(__fsub_rn(x2, x1), __fsub_rn(y2, y1));
            keep[r] = 1;
        }
        __syncthreads();
        for (int i = 0; i + 1 < n; ++i) {
            if (keep[i]) {
                float xi1 = bx1[i], yi1 = by1[i], xi2 = bx2[i], yi2 = by2[i];
                float ai  = barea[i];
                for (int j = i + 1 + tid; j < n; j += NT) {
                    if (!keep[j]) continue;
                    float xx1 = fmaxf(xi1, bx1[j]);
                    float yy1 = fmaxf(yi1, by1[j]);
                    float xx2 = fminf(xi2, bx2[j]);
                    float yy2 = fminf(yi2, by2[j]);
                    float iw  = fmaxf(__fsub_rn(xx2, xx1), 0.0f);
                    float ih  = fmaxf(__fsub_rn(yy2, yy1), 0.0f);
                    float inter = __fmul_rn(iw, ih);
                    float denom = __fadd_rn(__fsub_rn(__fadd_rn(ai, barea[j]), inter), 1e-7f);
                    if (__fdiv_rn(inter, denom) > 0.7f) keep[j] = 0;
                }
            }
            __syncthreads();
        }
        const float SCALE_F = 0.3333333333333333f;
        for (int r = tid; r < n; r += NT) {
            if (keep[r]) {
                float conf = __uint_as_float((unsigned)(keys[r] >> 32));
                o[r * 6 + 0] = __fdiv_rn(bx1[r], SCALE_F);
                o[r * 6 + 1] = __fdiv_rn(by1[r], SCALE_F);
                o[r * 6 + 2] = __fdiv_rn(bx2[r], SCALE_F);
                o[r * 6 + 3] = __fdiv_rn(by2[r], SCALE_F);
                o[r * 6 + 4] = conf;
            }
        }
    }
}

extern "C" void kernel_launch(void* const* d_in, const int* in_sizes, int n_in,
                              void* d_out, int out_size) {
    const float* preds = (const float*)d_in[0];
    float* out = (float*)d_out;

    score_compact_kernel<<<(BATCH * ANCH + 255) / 256, 256>>>(preds, out);
    sort_nms_out_kernel<<<BATCH, 1024>>>(preds, out);
}